// round 14
// baseline (speedup 1.0000x reference)
#include <cuda_runtime.h>
#include <cuda_bf16.h>
#include <cstdint>

// GlobalAttentionLayer, single fused pass, SINGLE LAUNCH (R14).
// pooled[b] = sum_n e^{g_n} * (states_n @ Wo + bo) / (sum_n e^{g_n} + eps)
//
// R14 = R13 (cp.async.bulk pipeline, tied-best 159.8us) with pipeline depth
// 2 -> 3 (48KB SMEM, still 4 CTA/SM): refill targets tile t+3, keeping the
// bulk-copy stream >=2 tiles ahead across __syncthreads jitter.
// Evidence from R10(LDG)/R13(TMA): ~6.5 TB/s is the achievable HBM read
// ceiling for this stream; this is a last-mile smoothing move.
//
// Inputs (metadata order):
//   d_in[0] states  float32 [N, 256]
//   d_in[1] seg_ids int32   [N]   (sorted)
//   d_in[2] Wg float32 [256,1]   d_in[3] bg float32 [1]
//   d_in[4] Wo float32 [256,2]   d_in[5] bo float32 [2]
// Output: float32 [B, 2], B = out_size/2

#define NBLOCKS   592
#define NTHREADS  256
#define MAXB      1024
#define STAGES    3
#define TILE_ROWS 16
#define ROW_BYTES 1024

__device__ float        g_accS [MAXB];
__device__ float        g_accV0[MAXB];
__device__ float        g_accV1[MAXB];
__device__ unsigned int g_done;

__device__ __forceinline__ uint32_t sptr(const void* p) {
    uint32_t a;
    asm("{ .reg .u64 t; cvta.to.shared.u64 t, %1; cvt.u32.u64 %0, t; }"
        : "=r"(a) : "l"(p));
    return a;
}
__device__ __forceinline__ void mbar_init(uint32_t mbar, uint32_t cnt) {
    asm volatile("mbarrier.init.shared.b64 [%0], %1;" :: "r"(mbar), "r"(cnt) : "memory");
}
__device__ __forceinline__ void mbar_expect_tx(uint32_t mbar, uint32_t bytes) {
    asm volatile("mbarrier.arrive.expect_tx.shared.b64 _, [%0], %1;"
                 :: "r"(mbar), "r"(bytes) : "memory");
}
__device__ __forceinline__ void mbar_wait(uint32_t mbar, uint32_t parity) {
    asm volatile(
        "{\n\t.reg .pred P;\n"
        "W%=:\n\t"
        "mbarrier.try_wait.parity.acquire.cta.shared::cta.b64 P, [%0], %1, 0x989680;\n\t"
        "@P bra D%=;\n\t"
        "bra W%=;\n"
        "D%=:\n\t}"
        :: "r"(mbar), "r"(parity) : "memory");
}
__device__ __forceinline__ void bulk_g2s(uint32_t dst, const void* src,
                                         uint32_t bytes, uint32_t mbar) {
    asm volatile(
        "cp.async.bulk.shared::cluster.global.mbarrier::complete_tx::bytes "
        "[%0], [%1], %2, [%3];"
        :: "r"(dst), "l"(src), "r"(bytes), "r"(mbar) : "memory");
}

__global__ __launch_bounds__(NTHREADS) void ga_main(
    const float* __restrict__ states,
    const int*   __restrict__ seg,
    const float* __restrict__ Wg,
    const float* __restrict__ bg,
    const float* __restrict__ Wo,
    const float* __restrict__ bo,
    float* __restrict__ out,
    int N, int B)
{
    __shared__ __align__(1024) unsigned char s_buf[STAGES][TILE_ROWS * ROW_BYTES];
    __shared__ unsigned long long            s_mbar[STAGES];
    __shared__ unsigned int                  s_last;

    const int tid  = threadIdx.x;
    const int lane = tid & 31;
    const int wid  = tid >> 5;

    const int chunk      = (N + (int)gridDim.x - 1) / (int)gridDim.x;
    const int chunkStart = (int)blockIdx.x * chunk;
    const int chunkEnd   = min(chunkStart + chunk, N);
    const int numRows    = max(chunkEnd - chunkStart, 0);
    const int numTiles   = (numRows + TILE_ROWS - 1) / TILE_ROWS;

    uint32_t mb[STAGES], buf[STAGES];
#pragma unroll
    for (int i = 0; i < STAGES; i++) {
        mb[i]  = sptr(&s_mbar[i]);
        buf[i] = sptr(&s_buf[i][0]);
    }

    const float bgv = bg[0];
    const float bo0 = bo[0];
    const float bo1 = bo[1];

    // Per-lane slice of the weight vectors: columns [lane*8, lane*8+8)
    const int c0 = lane * 8;
    float wg[8], wo0[8], wo1[8];
#pragma unroll
    for (int j = 0; j < 8; j++) {
        wg [j] = Wg[c0 + j];
        wo0[j] = Wo[(c0 + j) * 2 + 0];
        wo1[j] = Wo[(c0 + j) * 2 + 1];
    }

    if (tid == 0) {
#pragma unroll
        for (int i = 0; i < STAGES; i++) mbar_init(mb[i], 1);
    }
    __syncthreads();

    // depth-STAGES prefill
    if (tid == 0) {
        for (int p = 0; p < STAGES && p < numTiles; p++) {
            int rBase = p * TILE_ROWS;
            int rowsP = min(TILE_ROWS, numRows - rBase);
            uint32_t bytes = (uint32_t)rowsP * ROW_BYTES;
            mbar_expect_tx(mb[p], bytes);
            bulk_g2s(buf[p], states + (size_t)(chunkStart + rBase) * 256,
                     bytes, mb[p]);
        }
    }

    int   cur = -1;
    float aS  = 0.0f;
    float aV0 = 0.0f, aV1 = 0.0f;

#define FLUSH(SEGID)                                                        \
    do {                                                                    \
        float _v0 = aV0, _v1 = aV1;                                         \
        _Pragma("unroll")                                                   \
        for (int _o = 16; _o; _o >>= 1) {                                   \
            _v0 += __shfl_xor_sync(0xFFFFFFFFu, _v0, _o);                   \
            _v1 += __shfl_xor_sync(0xFFFFFFFFu, _v1, _o);                   \
        }                                                                   \
        if (lane == 0) {                                                    \
            atomicAdd(&g_accS [SEGID], aS);                                 \
            atomicAdd(&g_accV0[SEGID], fmaf(bo0, aS, _v0));                 \
            atomicAdd(&g_accV1[SEGID], fmaf(bo1, aS, _v1));                 \
        }                                                                   \
        aS = 0.0f; aV0 = 0.0f; aV1 = 0.0f;                                  \
    } while (0)

#define NODE1S(STG, R, GROW)                                                \
    do {                                                                    \
        const float4* rp = reinterpret_cast<const float4*>(                 \
            s_buf[STG] + (R) * ROW_BYTES) + lane * 2;                       \
        float4 xa = rp[0];                                                  \
        float4 xb = rp[1];                                                  \
        int sg = __ldg(&seg[GROW]);                                         \
        float x[8] = {xa.x, xa.y, xa.z, xa.w, xb.x, xb.y, xb.z, xb.w};      \
        float g = 0.f, p0 = 0.f, p1 = 0.f;                                  \
        _Pragma("unroll")                                                   \
        for (int j = 0; j < 8; j++) {                                       \
            g  = fmaf(x[j], wg [j], g);                                     \
            p0 = fmaf(x[j], wo0[j], p0);                                    \
            p1 = fmaf(x[j], wo1[j], p1);                                    \
        }                                                                   \
        _Pragma("unroll")                                                   \
        for (int off = 16; off; off >>= 1)                                  \
            g += __shfl_xor_sync(0xFFFFFFFFu, g, off);                      \
        float e = __expf(g + bgv);                                          \
        if (sg != cur) { if (cur >= 0) FLUSH(cur); cur = sg; }              \
        aS += e;                                                            \
        aV0 = fmaf(e, p0, aV0);                                             \
        aV1 = fmaf(e, p1, aV1);                                             \
    } while (0)

    int s = 0;           // stage index = t % STAGES (incremented manually)
    int phase = 0;       // parity flips each wrap
    for (int t = 0; t < numTiles; t++) {
        mbar_wait(mb[s], (uint32_t)phase);    // tile data visible (acquire)

        const int tBase = t * TILE_ROWS;
        const int rows  = min(TILE_ROWS, numRows - tBase);
        const int r0    = wid * 2;            // this warp's 2 rows

        if (r0 + 1 < rows) {
            const int g0 = chunkStart + tBase + r0;
            const int sv1 = __ldg(&seg[g0 + 1]);
            if (sv1 == cur) {
                // hot path: both rows in cur (ids sorted)
                const float4* rpa = reinterpret_cast<const float4*>(
                    s_buf[s] + (r0 + 0) * ROW_BYTES) + lane * 2;
                const float4* rpb = reinterpret_cast<const float4*>(
                    s_buf[s] + (r0 + 1) * ROW_BYTES) + lane * 2;
                float4 xa0 = rpa[0];
                float4 xb0 = rpa[1];
                float4 xa1 = rpb[0];
                float4 xb1 = rpb[1];

                float x0[8] = {xa0.x, xa0.y, xa0.z, xa0.w,
                               xb0.x, xb0.y, xb0.z, xb0.w};
                float x1[8] = {xa1.x, xa1.y, xa1.z, xa1.w,
                               xb1.x, xb1.y, xb1.z, xb1.w};

                float gg0 = 0.f, p00 = 0.f, p10 = 0.f;
                float gg1 = 0.f, p01 = 0.f, p11 = 0.f;
#pragma unroll
                for (int j = 0; j < 8; j++) {
                    gg0 = fmaf(x0[j], wg [j], gg0);
                    gg1 = fmaf(x1[j], wg [j], gg1);
                    p00 = fmaf(x0[j], wo0[j], p00);
                    p01 = fmaf(x1[j], wo0[j], p01);
                    p10 = fmaf(x0[j], wo1[j], p10);
                    p11 = fmaf(x1[j], wo1[j], p11);
                }
#pragma unroll
                for (int off = 16; off; off >>= 1) {
                    gg0 += __shfl_xor_sync(0xFFFFFFFFu, gg0, off);
                    gg1 += __shfl_xor_sync(0xFFFFFFFFu, gg1, off);
                }
                float e0 = __expf(gg0 + bgv);
                float e1 = __expf(gg1 + bgv);
                aS += e0 + e1;
                aV0 = fmaf(e0, p00, fmaf(e1, p01, aV0));
                aV1 = fmaf(e0, p10, fmaf(e1, p11, aV1));
            } else {
                NODE1S(s, r0 + 0, g0);
                NODE1S(s, r0 + 1, g0 + 1);
            }
        } else if (r0 < rows) {
            NODE1S(s, r0, chunkStart + tBase + r0);
        }

        __syncthreads();                      // buffer s fully consumed

        if (tid == 0 && t + STAGES < numTiles) {  // refill stage s: tile t+3
            int rBase = (t + STAGES) * TILE_ROWS;
            int rows2 = min(TILE_ROWS, numRows - rBase);
            uint32_t bytes = (uint32_t)rows2 * ROW_BYTES;
            mbar_expect_tx(mb[s], bytes);
            bulk_g2s(buf[s], states + (size_t)(chunkStart + rBase) * 256,
                     bytes, mb[s]);
        }

        if (++s == STAGES) { s = 0; phase ^= 1; }
    }

    if (cur >= 0) FLUSH(cur);
#undef FLUSH
#undef NODE1S

    // ---- fused finalize: last CTA to arrive does the [B,2] division ----
    __syncthreads();
    if (threadIdx.x == 0) {
        __threadfence();
        unsigned int prev = atomicAdd(&g_done, 1u);
        s_last = (prev == (unsigned int)gridDim.x - 1u) ? 1u : 0u;
    }
    __syncthreads();

    if (s_last) {
        __threadfence();
        int b = threadIdx.x;
        if (b < B) {
            float sv = g_accS [b];
            float v0 = g_accV0[b];
            float v1 = g_accV1[b];
            float d  = sv + 1e-16f;
            out[2 * b + 0] = v0 / d;
            out[2 * b + 1] = v1 / d;
            g_accS [b] = 0.0f;
            g_accV0[b] = 0.0f;
            g_accV1[b] = 0.0f;
        }
        if (threadIdx.x == 0) g_done = 0u;
    }
}

extern "C" void kernel_launch(void* const* d_in, const int* in_sizes, int n_in,
                              void* d_out, int out_size)
{
    const float* states = (const float*)d_in[0];
    const int*   seg    = (const int*)  d_in[1];
    const float* Wg     = (const float*)d_in[2];
    const float* bg     = (const float*)d_in[3];
    const float* Wo     = (const float*)d_in[4];
    const float* bo     = (const float*)d_in[5];
    float*       out    = (float*)d_out;

    const int N = in_sizes[1];
    const int B = out_size / 2;

    ga_main<<<NBLOCKS, NTHREADS>>>(states, seg, Wg, bg, Wo, bo, out, N, B);
}

// round 15
// speedup vs baseline: 1.0270x; 1.0270x over previous
#include <cuda_runtime.h>
#include <cuda_bf16.h>
#include <cstdint>

// GlobalAttentionLayer, single fused pass, SINGLE LAUNCH (R15 = R13 final).
// pooled[b] = sum_n e^{g_n} * (states_n @ Wo + bo) / (sum_n e^{g_n} + eps)
//
// CONVERGED KERNEL. cp.async.bulk depth-2 pipeline, 16-row (16KB) tiles,
// 8 warps x 2 rows/tile, deferred per-segment value reduction, fused
// last-CTA finalize. Both the LDG path (R10) and this TMA path saturate at
// ~6.5 TB/s / ~81% DRAM-active — the chip's achievable HBM read bandwidth
// for this stream (floor ~158us; this kernel: 159.8us).
// Confirmed-regressive: x4 unroll (R2,R4), dynamic scheduling (R8,R9),
// 5 CTA/SM (R11), L2 prefetch (R12), depth-3 pipeline / 49KB smem (R14).
//
// Inputs (metadata order):
//   d_in[0] states  float32 [N, 256]
//   d_in[1] seg_ids int32   [N]   (sorted)
//   d_in[2] Wg float32 [256,1]   d_in[3] bg float32 [1]
//   d_in[4] Wo float32 [256,2]   d_in[5] bo float32 [2]
// Output: float32 [B, 2], B = out_size/2

#define NBLOCKS   592
#define NTHREADS  256
#define MAXB      1024
#define TILE_ROWS 16
#define ROW_BYTES 1024

__device__ float        g_accS [MAXB];
__device__ float        g_accV0[MAXB];
__device__ float        g_accV1[MAXB];
__device__ unsigned int g_done;

__device__ __forceinline__ uint32_t sptr(const void* p) {
    uint32_t a;
    asm("{ .reg .u64 t; cvta.to.shared.u64 t, %1; cvt.u32.u64 %0, t; }"
        : "=r"(a) : "l"(p));
    return a;
}
__device__ __forceinline__ void mbar_init(uint32_t mbar, uint32_t cnt) {
    asm volatile("mbarrier.init.shared.b64 [%0], %1;" :: "r"(mbar), "r"(cnt) : "memory");
}
__device__ __forceinline__ void mbar_expect_tx(uint32_t mbar, uint32_t bytes) {
    asm volatile("mbarrier.arrive.expect_tx.shared.b64 _, [%0], %1;"
                 :: "r"(mbar), "r"(bytes) : "memory");
}
__device__ __forceinline__ void mbar_wait(uint32_t mbar, uint32_t parity) {
    asm volatile(
        "{\n\t.reg .pred P;\n"
        "W%=:\n\t"
        "mbarrier.try_wait.parity.acquire.cta.shared::cta.b64 P, [%0], %1, 0x989680;\n\t"
        "@P bra D%=;\n\t"
        "bra W%=;\n"
        "D%=:\n\t}"
        :: "r"(mbar), "r"(parity) : "memory");
}
__device__ __forceinline__ void bulk_g2s(uint32_t dst, const void* src,
                                         uint32_t bytes, uint32_t mbar) {
    asm volatile(
        "cp.async.bulk.shared::cluster.global.mbarrier::complete_tx::bytes "
        "[%0], [%1], %2, [%3];"
        :: "r"(dst), "l"(src), "r"(bytes), "r"(mbar) : "memory");
}

__global__ __launch_bounds__(NTHREADS) void ga_main(
    const float* __restrict__ states,
    const int*   __restrict__ seg,
    const float* __restrict__ Wg,
    const float* __restrict__ bg,
    const float* __restrict__ Wo,
    const float* __restrict__ bo,
    float* __restrict__ out,
    int N, int B)
{
    __shared__ __align__(1024) unsigned char s_buf[2][TILE_ROWS * ROW_BYTES];
    __shared__ unsigned long long            s_mbar[2];
    __shared__ unsigned int                  s_last;

    const int tid  = threadIdx.x;
    const int lane = tid & 31;
    const int wid  = tid >> 5;

    const int chunk      = (N + (int)gridDim.x - 1) / (int)gridDim.x;
    const int chunkStart = (int)blockIdx.x * chunk;
    const int chunkEnd   = min(chunkStart + chunk, N);
    const int numRows    = max(chunkEnd - chunkStart, 0);
    const int numTiles   = (numRows + TILE_ROWS - 1) / TILE_ROWS;

    const uint32_t mb[2]  = { sptr(&s_mbar[0]), sptr(&s_mbar[1]) };
    const uint32_t buf[2] = { sptr(&s_buf[0][0]), sptr(&s_buf[1][0]) };

    const float bgv = bg[0];
    const float bo0 = bo[0];
    const float bo1 = bo[1];

    // Per-lane slice of the weight vectors: columns [lane*8, lane*8+8)
    const int c0 = lane * 8;
    float wg[8], wo0[8], wo1[8];
#pragma unroll
    for (int j = 0; j < 8; j++) {
        wg [j] = Wg[c0 + j];
        wo0[j] = Wo[(c0 + j) * 2 + 0];
        wo1[j] = Wo[(c0 + j) * 2 + 1];
    }

    if (tid == 0) {
        mbar_init(mb[0], 1);
        mbar_init(mb[1], 1);
    }
    __syncthreads();

    // depth-2 prefill
    if (tid == 0) {
        for (int p = 0; p < 2 && p < numTiles; p++) {
            int rBase = p * TILE_ROWS;
            int rowsP = min(TILE_ROWS, numRows - rBase);
            uint32_t bytes = (uint32_t)rowsP * ROW_BYTES;
            mbar_expect_tx(mb[p], bytes);
            bulk_g2s(buf[p], states + (size_t)(chunkStart + rBase) * 256,
                     bytes, mb[p]);
        }
    }

    int   cur = -1;
    float aS  = 0.0f;
    float aV0 = 0.0f, aV1 = 0.0f;

#define FLUSH(SEGID)                                                        \
    do {                                                                    \
        float _v0 = aV0, _v1 = aV1;                                         \
        _Pragma("unroll")                                                   \
        for (int _o = 16; _o; _o >>= 1) {                                   \
            _v0 += __shfl_xor_sync(0xFFFFFFFFu, _v0, _o);                   \
            _v1 += __shfl_xor_sync(0xFFFFFFFFu, _v1, _o);                   \
        }                                                                   \
        if (lane == 0) {                                                    \
            atomicAdd(&g_accS [SEGID], aS);                                 \
            atomicAdd(&g_accV0[SEGID], fmaf(bo0, aS, _v0));                 \
            atomicAdd(&g_accV1[SEGID], fmaf(bo1, aS, _v1));                 \
        }                                                                   \
        aS = 0.0f; aV0 = 0.0f; aV1 = 0.0f;                                  \
    } while (0)

    // single-row accumulate from smem
#define NODE1S(BUFA, R, GROW)                                               \
    do {                                                                    \
        const float4* rp = reinterpret_cast<const float4*>(                 \
            s_buf[BUFA] + (R) * ROW_BYTES) + lane * 2;                      \
        float4 xa = rp[0];                                                  \
        float4 xb = rp[1];                                                  \
        int sg = __ldg(&seg[GROW]);                                         \
        float x[8] = {xa.x, xa.y, xa.z, xa.w, xb.x, xb.y, xb.z, xb.w};      \
        float g = 0.f, p0 = 0.f, p1 = 0.f;                                  \
        _Pragma("unroll")                                                   \
        for (int j = 0; j < 8; j++) {                                       \
            g  = fmaf(x[j], wg [j], g);                                     \
            p0 = fmaf(x[j], wo0[j], p0);                                    \
            p1 = fmaf(x[j], wo1[j], p1);                                    \
        }                                                                   \
        _Pragma("unroll")                                                   \
        for (int off = 16; off; off >>= 1)                                  \
            g += __shfl_xor_sync(0xFFFFFFFFu, g, off);                      \
        float e = __expf(g + bgv);                                          \
        if (sg != cur) { if (cur >= 0) FLUSH(cur); cur = sg; }              \
        aS += e;                                                            \
        aV0 = fmaf(e, p0, aV0);                                             \
        aV1 = fmaf(e, p1, aV1);                                             \
    } while (0)

    for (int t = 0; t < numTiles; t++) {
        const int s  = t & 1;
        const uint32_t pf = (uint32_t)(t >> 1) & 1u;

        mbar_wait(mb[s], pf);                 // tile data visible (acquire)

        const int tBase = t * TILE_ROWS;
        const int rows  = min(TILE_ROWS, numRows - tBase);
        const int r0    = wid * 2;            // this warp's 2 rows

        if (r0 + 1 < rows) {
            const int g0 = chunkStart + tBase + r0;
            const int sv1 = __ldg(&seg[g0 + 1]);
            if (sv1 == cur) {
                // hot path: both rows in cur (ids sorted)
                const float4* rpa = reinterpret_cast<const float4*>(
                    s_buf[s] + (r0 + 0) * ROW_BYTES) + lane * 2;
                const float4* rpb = reinterpret_cast<const float4*>(
                    s_buf[s] + (r0 + 1) * ROW_BYTES) + lane * 2;
                float4 xa0 = rpa[0];
                float4 xb0 = rpa[1];
                float4 xa1 = rpb[0];
                float4 xb1 = rpb[1];

                float x0[8] = {xa0.x, xa0.y, xa0.z, xa0.w,
                               xb0.x, xb0.y, xb0.z, xb0.w};
                float x1[8] = {xa1.x, xa1.y, xa1.z, xa1.w,
                               xb1.x, xb1.y, xb1.z, xb1.w};

                float gg0 = 0.f, p00 = 0.f, p10 = 0.f;
                float gg1 = 0.f, p01 = 0.f, p11 = 0.f;
#pragma unroll
                for (int j = 0; j < 8; j++) {
                    gg0 = fmaf(x0[j], wg [j], gg0);
                    gg1 = fmaf(x1[j], wg [j], gg1);
                    p00 = fmaf(x0[j], wo0[j], p00);
                    p01 = fmaf(x1[j], wo0[j], p01);
                    p10 = fmaf(x0[j], wo1[j], p10);
                    p11 = fmaf(x1[j], wo1[j], p11);
                }
#pragma unroll
                for (int off = 16; off; off >>= 1) {
                    gg0 += __shfl_xor_sync(0xFFFFFFFFu, gg0, off);
                    gg1 += __shfl_xor_sync(0xFFFFFFFFu, gg1, off);
                }
                float e0 = __expf(gg0 + bgv);
                float e1 = __expf(gg1 + bgv);
                aS += e0 + e1;
                aV0 = fmaf(e0, p00, fmaf(e1, p01, aV0));
                aV1 = fmaf(e0, p10, fmaf(e1, p11, aV1));
            } else {
                NODE1S(s, r0 + 0, g0);
                NODE1S(s, r0 + 1, g0 + 1);
            }
        } else if (r0 < rows) {
            NODE1S(s, r0, chunkStart + tBase + r0);
        }

        __syncthreads();                      // buffer s fully consumed

        if (tid == 0 && t + 2 < numTiles) {   // refill stage s with tile t+2
            int rBase = (t + 2) * TILE_ROWS;
            int rows2 = min(TILE_ROWS, numRows - rBase);
            uint32_t bytes = (uint32_t)rows2 * ROW_BYTES;
            mbar_expect_tx(mb[s], bytes);
            bulk_g2s(buf[s], states + (size_t)(chunkStart + rBase) * 256,
                     bytes, mb[s]);
        }
    }

    if (cur >= 0) FLUSH(cur);
#undef FLUSH
#undef NODE1S

    // ---- fused finalize: last CTA to arrive does the [B,2] division ----
    __syncthreads();
    if (threadIdx.x == 0) {
        __threadfence();
        unsigned int prev = atomicAdd(&g_done, 1u);
        s_last = (prev == (unsigned int)gridDim.x - 1u) ? 1u : 0u;
    }
    __syncthreads();

    if (s_last) {
        __threadfence();
        int b = threadIdx.x;
        if (b < B) {
            float sv = g_accS [b];
            float v0 = g_accV0[b];
            float v1 = g_accV1[b];
            float d  = sv + 1e-16f;
            out[2 * b + 0] = v0 / d;
            out[2 * b + 1] = v1 / d;
            g_accS [b] = 0.0f;
            g_accV0[b] = 0.0f;
            g_accV1[b] = 0.0f;
        }
        if (threadIdx.x == 0) g_done = 0u;
    }
}

extern "C" void kernel_launch(void* const* d_in, const int* in_sizes, int n_in,
                              void* d_out, int out_size)
{
    const float* states = (const float*)d_in[0];
    const int*   seg    = (const int*)  d_in[1];
    const float* Wg     = (const float*)d_in[2];
    const float* bg     = (const float*)d_in[3];
    const float* Wo     = (const float*)d_in[4];
    const float* bo     = (const float*)d_in[5];
    float*       out    = (float*)d_out;

    const int N = in_sizes[1];
    const int B = out_size / 2;

    ga_main<<<NBLOCKS, NTHREADS>>>(states, seg, Wg, bg, Wo, bo, out, N, B);
}

// round 16
// speedup vs baseline: 1.0494x; 1.0219x over previous
#include <cuda_runtime.h>
#include <cuda_bf16.h>

// GlobalAttentionLayer, single fused pass, SINGLE LAUNCH (FINAL = R10).
// pooled[b] = sum_n e^{g_n} * (states_n @ Wo + bo) / (sum_n e^{g_n} + eps)
//
// CONVERGED KERNEL (best measured: 159.8us; HBM floor ~158.5us at the chip's
// measured 6.49 TB/s achievable read bandwidth — confirmed identically by an
// independent cp.async.bulk/TMA pipeline in R13).
// Structure: segment-outer (binary search over sorted ids) / branch-free
// node-inner x2 loop, 4 front-batched LDG.128 + __ldcs streaming, deferred
// per-segment value reduction (gate-only per-node butterfly), fused
// last-CTA finalize, .bss-zero accumulator invariant restored in epilogue.
// Confirmed-regressive: x4 unroll (R2,R4), dynamic scheduling (R8,R9),
// 5 CTA/SM (R11), L2 prefetch (R12), 3-stage TMA / 49KB smem (R14).
//
// Inputs (metadata order):
//   d_in[0] states  float32 [N, 256]
//   d_in[1] seg_ids int32   [N]   (sorted)
//   d_in[2] Wg float32 [256,1]   d_in[3] bg float32 [1]
//   d_in[4] Wo float32 [256,2]   d_in[5] bo float32 [2]
// Output: float32 [B, 2], B = out_size/2

#define NBLOCKS  592
#define NTHREADS 256
#define MAXB     1024

__device__ float        g_accS [MAXB];   // zero at module load; epilogue re-zeros
__device__ float        g_accV0[MAXB];
__device__ float        g_accV1[MAXB];
__device__ unsigned int g_done;          // zero at module load; epilogue re-zeros

__global__ __launch_bounds__(NTHREADS) void ga_main(
    const float* __restrict__ states,
    const int*   __restrict__ seg,
    const float* __restrict__ Wg,
    const float* __restrict__ bg,
    const float* __restrict__ Wo,
    const float* __restrict__ bo,
    float* __restrict__ out,
    int N, int B)
{
    const int lane   = threadIdx.x & 31;
    const int gwarp  = (blockIdx.x * blockDim.x + threadIdx.x) >> 5;
    const int nwarps = (gridDim.x * blockDim.x) >> 5;
    const int chunk  = (N + nwarps - 1) / nwarps;
    const int start  = gwarp * chunk;
    const int end    = min(start + chunk, N);

    const float bgv = bg[0];
    const float bo0 = bo[0];
    const float bo1 = bo[1];

    if (start < end) {
        // Per-lane slice of the weight vectors: columns [lane*8, lane*8+8)
        const int c0 = lane * 8;
        float wg[8], wo0[8], wo1[8];
#pragma unroll
        for (int j = 0; j < 8; j++) {
            wg [j] = Wg[c0 + j];
            wo0[j] = Wo[(c0 + j) * 2 + 0];
            wo1[j] = Wo[(c0 + j) * 2 + 1];
        }

        const float4* base = reinterpret_cast<const float4*>(states);

        int n = start;
        while (n < end) {
            const int s = seg[n];            // current segment id (lane-uniform)

            // binary search: first index in (n, end) with seg != s
            int lo = n + 1, hi = end;
            while (lo < hi) {
                int mid = (lo + hi) >> 1;
                if (seg[mid] == s) lo = mid + 1; else hi = mid;
            }
            const int sEnd = lo;

            float aS  = 0.0f;                // sum of e (lane-uniform)
            float aV0 = 0.0f, aV1 = 0.0f;    // per-lane partials of e * p_lane

            int m = n;
            // ---- branch-free inner loop: 2 nodes/iter, streaming loads ----
            for (; m + 2 <= sEnd; m += 2) {
                const float4* r0 = base + (size_t)(m + 0) * 64 + lane * 2;
                const float4* r1 = base + (size_t)(m + 1) * 64 + lane * 2;
                float4 xa0 = __ldcs(r0);
                float4 xb0 = __ldcs(r0 + 1);
                float4 xa1 = __ldcs(r1);
                float4 xb1 = __ldcs(r1 + 1);

                float x0[8] = {xa0.x, xa0.y, xa0.z, xa0.w,
                               xb0.x, xb0.y, xb0.z, xb0.w};
                float x1[8] = {xa1.x, xa1.y, xa1.z, xa1.w,
                               xb1.x, xb1.y, xb1.z, xb1.w};

                float g0 = 0.f, p00 = 0.f, p10 = 0.f;
                float g1 = 0.f, p01 = 0.f, p11 = 0.f;
#pragma unroll
                for (int j = 0; j < 8; j++) {
                    g0  = fmaf(x0[j], wg [j], g0);
                    g1  = fmaf(x1[j], wg [j], g1);
                    p00 = fmaf(x0[j], wo0[j], p00);
                    p01 = fmaf(x1[j], wo0[j], p01);
                    p10 = fmaf(x0[j], wo1[j], p10);
                    p11 = fmaf(x1[j], wo1[j], p11);
                }

                // two interleaved butterfly chains (gates only)
#pragma unroll
                for (int off = 16; off; off >>= 1) {
                    g0 += __shfl_xor_sync(0xFFFFFFFFu, g0, off);
                    g1 += __shfl_xor_sync(0xFFFFFFFFu, g1, off);
                }

                float e0 = __expf(g0 + bgv);
                float e1 = __expf(g1 + bgv);

                aS += e0 + e1;
                aV0 = fmaf(e0, p00, fmaf(e1, p01, aV0));
                aV1 = fmaf(e0, p10, fmaf(e1, p11, aV1));
            }

            // ---- tail (at most 1 node of this segment) ----
            for (; m < sEnd; m++) {
                const float4* row = base + (size_t)m * 64 + lane * 2;
                float4 xa = __ldcs(row);
                float4 xb = __ldcs(row + 1);

                float x[8] = {xa.x, xa.y, xa.z, xa.w,
                              xb.x, xb.y, xb.z, xb.w};
                float g = 0.f, p0 = 0.f, p1 = 0.f;
#pragma unroll
                for (int j = 0; j < 8; j++) {
                    g  = fmaf(x[j], wg [j], g);
                    p0 = fmaf(x[j], wo0[j], p0);
                    p1 = fmaf(x[j], wo1[j], p1);
                }
#pragma unroll
                for (int off = 16; off; off >>= 1)
                    g += __shfl_xor_sync(0xFFFFFFFFu, g, off);

                float e = __expf(g + bgv);
                aS += e;
                aV0 = fmaf(e, p0, aV0);
                aV1 = fmaf(e, p1, aV1);
            }

            // ---- flush this segment (once per segment per warp) ----
            {
                float v0 = aV0, v1 = aV1;
#pragma unroll
                for (int off = 16; off; off >>= 1) {
                    v0 += __shfl_xor_sync(0xFFFFFFFFu, v0, off);
                    v1 += __shfl_xor_sync(0xFFFFFFFFu, v1, off);
                }
                if (lane == 0) {
                    atomicAdd(&g_accS [s], aS);
                    atomicAdd(&g_accV0[s], fmaf(bo0, aS, v0));
                    atomicAdd(&g_accV1[s], fmaf(bo1, aS, v1));
                }
            }

            n = sEnd;
        }
    }

    // ---- fused finalize: last CTA to arrive does the [B,2] division ----
    __syncthreads();                       // all warps' flush atomics issued
    __shared__ unsigned int s_last;
    if (threadIdx.x == 0) {
        __threadfence();                   // order atomics before the counter
        unsigned int prev = atomicAdd(&g_done, 1u);
        s_last = (prev == (unsigned int)gridDim.x - 1u) ? 1u : 0u;
    }
    __syncthreads();

    if (s_last) {
        __threadfence();                   // acquire: see all CTAs' atomics
        int b = threadIdx.x;
        if (b < B) {
            float s  = g_accS [b];
            float v0 = g_accV0[b];
            float v1 = g_accV1[b];
            float d  = s + 1e-16f;
            out[2 * b + 0] = v0 / d;
            out[2 * b + 1] = v1 / d;
            // restore the zero-invariant for the next call / graph replay
            g_accS [b] = 0.0f;
            g_accV0[b] = 0.0f;
            g_accV1[b] = 0.0f;
        }
        if (threadIdx.x == 0) g_done = 0u;
    }
}

extern "C" void kernel_launch(void* const* d_in, const int* in_sizes, int n_in,
                              void* d_out, int out_size)
{
    const float* states = (const float*)d_in[0];
    const int*   seg    = (const int*)  d_in[1];
    const float* Wg     = (const float*)d_in[2];
    const float* bg     = (const float*)d_in[3];
    const float* Wo     = (const float*)d_in[4];
    const float* bo     = (const float*)d_in[5];
    float*       out    = (float*)d_out;

    const int N = in_sizes[1];
    const int B = out_size / 2;

    ga_main<<<NBLOCKS, NTHREADS>>>(states, seg, Wg, bg, Wo, bo, out, N, B);
}